// round 12
// baseline (speedup 1.0000x reference)
#include <cuda_runtime.h>
#include <cuda_bf16.h>
#include <mma.h>
#include <cstdint>

using namespace nvcuda;

#define N_NODES 50000
#define N_EDGES 600000
#define FEAT 128
#define PADM 50048        // 782 * 64
#define NBLK_SCAN 196     // ceil(50000/256)
#define NTILES 782        // PADM / 64
#define GEMM_GRID 152     // 1 CTA per SM on GB300

// ---------------- device scratch ----------------
__device__ int   g_idx64;
__device__ int   g_pos_arange;
__device__ int   g_cnt[N_NODES];
__device__ int   g_cursor[N_NODES];
__device__ int   g_part[N_NODES];
__device__ int   g_blksum[NBLK_SCAN];
__device__ int   g_rowstart[N_NODES + 1];
__device__ float g_inv[N_NODES];
__device__ int   g_csr[N_EDGES];

__device__ float g_agg[(size_t)PADM * FEAT];   // fp32 aggregated features (pads stay 0)
__device__ float g_h1 [(size_t)PADM * FEAT];   // fp32 layer-1 output (pads stay 0)
// B[layer][n][k], k in [0,256): k<128 -> Wl[k][n], else Wr[k-128][n]
__device__ __nv_bfloat16 g_Bhi[2 * 128 * 256];
__device__ __nv_bfloat16 g_Blo[2 * 128 * 256];

__device__ __forceinline__ int load_idx(const void* p, long long i, int is64) {
    return is64 ? (int)((const long long*)p)[i] : ((const int*)p)[i];
}
__device__ __forceinline__ unsigned pack_bf16x2(float a, float b) {
    unsigned short ua = __bfloat16_as_ushort(__float2bfloat16_rn(a));
    unsigned short ub = __bfloat16_as_ushort(__float2bfloat16_rn(b));
    return (unsigned)ua | ((unsigned)ub << 16);
}
__device__ __forceinline__ float bf16v(float v) {
    return __bfloat162float(__float2bfloat16_rn(v));
}

// ---------------- detect index dtype + pos==arange (parallel, 1 load/thread) ----------------
__global__ void k_detect(const unsigned* __restrict__ w, const void* __restrict__ pos) {
    int tid = threadIdx.x;   // 256 threads
    int ok64 = (w[2 * tid + 1] == 0u) ? 1 : 0;
    int is64 = __syncthreads_and(ok64);
    if (tid == 0) g_idx64 = is64;
    int idx = tid * 195;     // spans [0, 49725]
    int ar = (load_idx(pos, idx, is64) == idx) ? 1 : 0;
    int arall = __syncthreads_and(ar);
    if (tid == 0) g_pos_arange = arall;
}

// ---------------- init: zero out-tail + prep weights + reset counters ----------------
__global__ void k_init(float* __restrict__ out, int out_n,
                       const float* __restrict__ Wl1, const float* __restrict__ Wr1,
                       const float* __restrict__ Wl2, const float* __restrict__ Wr2) {
    int stride = gridDim.x * blockDim.x;
    int gid = blockIdx.x * blockDim.x + threadIdx.x;

    float4 z = make_float4(0.f, 0.f, 0.f, 0.f);
    int zstart4 = g_pos_arange ? (N_NODES * FEAT) >> 2 : 0;
    int on4 = out_n >> 2;
    for (int i = zstart4 + gid; i < on4; i += stride) ((float4*)out)[i] = z;

    for (int id = gid; id < 2 * 128 * 256; id += stride) {
        int layer = id >> 15;
        int rem = id & 32767;
        int n = rem >> 8;
        int k = rem & 255;
        const float* Wl = layer ? Wl2 : Wl1;
        const float* Wr = layer ? Wr2 : Wr1;
        float v = (k < 128) ? Wl[k * 128 + n] : Wr[(k - 128) * 128 + n];
        __nv_bfloat16 h = __float2bfloat16_rn(v);
        g_Bhi[id] = h;
        g_Blo[id] = __float2bfloat16_rn(v - __bfloat162float(h));
    }

    for (int i = gid; i < N_NODES; i += stride) { g_cnt[i] = 0; g_cursor[i] = 0; }
}

__global__ void k_hist(const void* __restrict__ ei) {
    int e = blockIdx.x * blockDim.x + threadIdx.x;
    if (e >= N_EDGES) return;
    int d = load_idx(ei, (long long)N_EDGES + e, g_idx64);
    if ((unsigned)d < (unsigned)N_NODES) atomicAdd(&g_cnt[d], 1);
}

// ---------------- 2-kernel coalesced scan ----------------
__device__ __forceinline__ int blockscan256_excl(int v, int* ws) {
    int tid = threadIdx.x, lane = tid & 31, w = tid >> 5;
    int incl = v;
    #pragma unroll
    for (int o = 1; o < 32; o <<= 1) {
        int t = __shfl_up_sync(0xFFFFFFFFu, incl, o);
        if (lane >= o) incl += t;
    }
    if (lane == 31) ws[w] = incl;
    __syncthreads();
    if (w == 0) {
        int s = (lane < 8) ? ws[lane] : 0;
        #pragma unroll
        for (int o = 1; o < 8; o <<= 1) {
            int t = __shfl_up_sync(0xFFFFFFFFu, s, o);
            if (lane >= o) s += t;
        }
        if (lane < 8) ws[lane] = s;
    }
    __syncthreads();
    return incl - v + (w ? ws[w - 1] : 0);
}

__global__ void k_scan_part() {
    __shared__ int ws[8];
    int i = blockIdx.x * 256 + threadIdx.x;
    int v = (i < N_NODES) ? g_cnt[i] : 0;
    int excl = blockscan256_excl(v, ws);
    if (i < N_NODES) g_part[i] = excl;
    if (threadIdx.x == 255) g_blksum[blockIdx.x] = excl + v;
}

__global__ void k_scan_add() {
    __shared__ int ws[8];
    __shared__ int s_off;
    int tid = threadIdx.x, lane = tid & 31, w = tid >> 5;
    int bid = blockIdx.x;
    int v = (tid < NBLK_SCAN && tid < bid) ? g_blksum[tid] : 0;
    #pragma unroll
    for (int o = 16; o > 0; o >>= 1) v += __shfl_down_sync(0xFFFFFFFFu, v, o);
    if (lane == 0) ws[w] = v;
    __syncthreads();
    if (tid == 0) {
        int t = 0;
        #pragma unroll
        for (int j = 0; j < 8; j++) t += ws[j];
        s_off = t;
    }
    __syncthreads();
    int off = s_off;
    int i = bid * 256 + tid;
    if (i < N_NODES) {
        g_rowstart[i] = g_part[i] + off;
        g_inv[i] = 1.0f / fmaxf((float)g_cnt[i], 1.0f);
    }
    if (bid == NBLK_SCAN - 1 && tid == 0)
        g_rowstart[N_NODES] = off + g_blksum[bid];
}

__global__ void k_scatter(const void* __restrict__ ei) {
    int e = blockIdx.x * blockDim.x + threadIdx.x;
    if (e >= N_EDGES) return;
    int is64 = g_idx64;
    int s = load_idx(ei, e, is64);
    int d = load_idx(ei, (long long)N_EDGES + e, is64);
    if ((unsigned)d >= (unsigned)N_NODES || (unsigned)s >= (unsigned)N_NODES) return;
    int p = g_rowstart[d] + atomicAdd(&g_cursor[d], 1);
    if (p < N_EDGES) g_csr[p] = s;
}

// ---------------- aggregation: one warp per node, 4-way unrolled gather (fp32 out) ----------------
__global__ void k_agg(const float* __restrict__ feat_x, int layer2) {
    const float* __restrict__ feat = layer2 ? g_h1 : feat_x;
    int gw = (blockIdx.x * blockDim.x + threadIdx.x) >> 5;
    int lane = threadIdx.x & 31;
    if (gw >= N_NODES) return;
    int s = g_rowstart[gw], e = g_rowstart[gw + 1];
    float4 acc = make_float4(0.f, 0.f, 0.f, 0.f);
    int i = s;
    for (; i + 4 <= e; i += 4) {
        int s0 = g_csr[i + 0], s1 = g_csr[i + 1], s2 = g_csr[i + 2], s3 = g_csr[i + 3];
        float4 v0 = *(const float4*)(feat + (size_t)s0 * FEAT + lane * 4);
        float4 v1 = *(const float4*)(feat + (size_t)s1 * FEAT + lane * 4);
        float4 v2 = *(const float4*)(feat + (size_t)s2 * FEAT + lane * 4);
        float4 v3 = *(const float4*)(feat + (size_t)s3 * FEAT + lane * 4);
        acc.x += v0.x + v1.x + v2.x + v3.x;
        acc.y += v0.y + v1.y + v2.y + v3.y;
        acc.z += v0.z + v1.z + v2.z + v3.z;
        acc.w += v0.w + v1.w + v2.w + v3.w;
    }
    for (; i < e; i++) {
        int src = g_csr[i];
        float4 v = *(const float4*)(feat + (size_t)src * FEAT + lane * 4);
        acc.x += v.x; acc.y += v.y; acc.z += v.z; acc.w += v.w;
    }
    float inv = g_inv[gw];
    acc.x *= inv; acc.y *= inv; acc.z *= inv; acc.w *= inv;
    *(float4*)(g_agg + (size_t)gw * FEAT + lane * 4) = acc;
}

// ---------------- B-resident persistent bf16 3-split wmma GEMM ----------------
// B (hi+lo, 128x256 padded) lives in smem for the whole kernel; each CTA streams
// ~5 M-tiles of 64 rows, staging full-K A tiles (fp32 -> bf16 hi/lo split) once per tile.
typedef wmma::fragment<wmma::matrix_a, 16, 16, 16, __nv_bfloat16, wmma::row_major> FragA;
typedef wmma::fragment<wmma::matrix_b, 16, 16, 16, __nv_bfloat16, wmma::col_major> FragB;
typedef wmma::fragment<wmma::accumulator, 16, 16, 16, float> FragC;

#define KP2 264   // padded full-K stride (256 + 8 elems)

// smem byte offsets
#define OFF_B0 0                               // B hi: 128 x KP2 bf16 = 67584
#define OFF_B1 67584                           // B lo
#define OFF_A0 135168                          // A hi: 64 x KP2 bf16 = 33792
#define OFF_A1 168960                          // A lo
#define OFF_CS 135168                          // epilogue f32 64x128 (reuses A region)
#define GEMM_SMEM 202752

__global__ void __launch_bounds__(256, 1) k_gemm(
    const float* __restrict__ xin,
    const float* __restrict__ bias,
    float* __restrict__ out2, const void* __restrict__ pos, int layer2)
{
    extern __shared__ __align__(16) char smraw[];
    __nv_bfloat16* sB0 = (__nv_bfloat16*)(smraw + OFF_B0);
    __nv_bfloat16* sB1 = (__nv_bfloat16*)(smraw + OFF_B1);
    __nv_bfloat16* sA0 = (__nv_bfloat16*)(smraw + OFF_A0);
    __nv_bfloat16* sA1 = (__nv_bfloat16*)(smraw + OFF_A1);
    float* cs = (float*)(smraw + OFF_CS);

    const float* selfF = layer2 ? g_h1 : xin;
    const __nv_bfloat16* BH = g_Bhi + (size_t)layer2 * 128 * 256;
    const __nv_bfloat16* BL = g_Blo + (size_t)layer2 * 128 * 256;

    int tid = threadIdx.x;
    int warp = tid >> 5;
    int wm = warp & 1;    // 2 M warps (32 rows each)
    int wn = warp >> 1;   // 4 N warps (32 cols each)
    int is64 = g_idx64;

    // ---- load full B (hi+lo) into smem once: 4096 groups of 8 bf16, 16/thread ----
    #pragma unroll
    for (int i = 0; i < 16; i++) {
        int g = tid + i * 256;          // 0..4095
        int row = g >> 5;               // 0..127
        int kg = (g & 31) * 8;          // 0..248
        size_t src = (size_t)row * 256 + kg;
        int dst = row * KP2 + kg;
        *(uint4*)(sB0 + dst) = *(const uint4*)(BH + src);
        *(uint4*)(sB1 + dst) = *(const uint4*)(BL + src);
    }
    __syncthreads();

    // ---- loop over M-tiles ----
    for (int tile = blockIdx.x; tile < NTILES; tile += GEMM_GRID) {
        int m0 = tile * 64;

        // stage A tile: 64 rows x 256 k fp32 -> bf16 hi/lo; 2048 groups of 8, 8/thread
        #pragma unroll
        for (int i = 0; i < 8; i++) {
            int g = tid + i * 256;      // 0..2047
            int row = g >> 5;           // 0..63
            int kg = (g & 31) * 8;      // 0..248
            float4 f0 = make_float4(0.f, 0.f, 0.f, 0.f), f1 = f0;
            if (m0 + row < N_NODES) {
                const float* Aarr = (kg < 128) ? g_agg : selfF;
                int kofs = (kg < 128) ? kg : (kg - 128);
                size_t asrc = (size_t)(m0 + row) * FEAT + kofs;
                f0 = *(const float4*)(Aarr + asrc);
                f1 = *(const float4*)(Aarr + asrc + 4);
            }
            uint4 hv, lv;
            hv.x = pack_bf16x2(f0.x, f0.y);
            hv.y = pack_bf16x2(f0.z, f0.w);
            hv.z = pack_bf16x2(f1.x, f1.y);
            hv.w = pack_bf16x2(f1.z, f1.w);
            lv.x = pack_bf16x2(f0.x - bf16v(f0.x), f0.y - bf16v(f0.y));
            lv.y = pack_bf16x2(f0.z - bf16v(f0.z), f0.w - bf16v(f0.w));
            lv.z = pack_bf16x2(f1.x - bf16v(f1.x), f1.y - bf16v(f1.y));
            lv.w = pack_bf16x2(f1.z - bf16v(f1.z), f1.w - bf16v(f1.w));
            int dst = row * KP2 + kg;
            *(uint4*)(sA0 + dst) = hv;
            *(uint4*)(sA1 + dst) = lv;
        }
        __syncthreads();

        // compute: all 16 k-steps, no intervening syncs
        FragC c[2][2];
        #pragma unroll
        for (int i = 0; i < 2; i++)
            #pragma unroll
            for (int j = 0; j < 2; j++)
                wmma::fill_fragment(c[i][j], 0.0f);

        #pragma unroll 4
        for (int ks = 0; ks < 16; ks++) {
            FragA ah[2], al[2];
            #pragma unroll
            for (int i = 0; i < 2; i++) {
                wmma::load_matrix_sync(ah[i], sA0 + (wm * 32 + i * 16) * KP2 + ks * 16, KP2);
                wmma::load_matrix_sync(al[i], sA1 + (wm * 32 + i * 16) * KP2 + ks * 16, KP2);
            }
            FragB bh[2], bl[2];
            #pragma unroll
            for (int j = 0; j < 2; j++) {
                wmma::load_matrix_sync(bh[j], sB0 + (wn * 32 + j * 16) * KP2 + ks * 16, KP2);
                wmma::load_matrix_sync(bl[j], sB1 + (wn * 32 + j * 16) * KP2 + ks * 16, KP2);
            }
            #pragma unroll
            for (int i = 0; i < 2; i++)
                #pragma unroll
                for (int j = 0; j < 2; j++) {
                    wmma::mma_sync(c[i][j], ah[i], bh[j], c[i][j]);
                    wmma::mma_sync(c[i][j], al[i], bh[j], c[i][j]);
                    wmma::mma_sync(c[i][j], ah[i], bl[j], c[i][j]);
                }
        }
        __syncthreads();   // A region about to be reused as cs

        // epilogue: stage C to smem (64 x 128 f32), bias + relu + write
        #pragma unroll
        for (int i = 0; i < 2; i++)
            #pragma unroll
            for (int j = 0; j < 2; j++)
                wmma::store_matrix_sync(&cs[(wm * 32 + i * 16) * 128 + wn * 32 + j * 16],
                                        c[i][j], 128, wmma::mem_row_major);
        __syncthreads();

        #pragma unroll
        for (int it = 0; it < 8; it++) {
            int idx = (it * 256 + tid) * 4;    // 0..8188 -> 64x128
            int m = idx >> 7;
            int n = idx & 127;
            int row = m0 + m;
            if (row < N_NODES) {
                float v0 = fmaxf(cs[idx + 0] + bias[n + 0], 0.0f);
                float v1 = fmaxf(cs[idx + 1] + bias[n + 1], 0.0f);
                float v2 = fmaxf(cs[idx + 2] + bias[n + 2], 0.0f);
                float v3 = fmaxf(cs[idx + 3] + bias[n + 3], 0.0f);
                if (!layer2) {
                    *(float4*)(g_h1 + (size_t)row * FEAT + n) = make_float4(v0, v1, v2, v3);
                } else {
                    long long orow = (long long)load_idx(pos, row, is64);
                    *(float4*)(out2 + (size_t)orow * FEAT + n) = make_float4(v0, v1, v2, v3);
                }
            }
        }
        __syncthreads();   // cs/A region reused next iteration
    }
}

// ---------------- launch ----------------
extern "C" void kernel_launch(void* const* d_in, const int* in_sizes, int n_in,
                              void* d_out, int out_size) {
    int wi = (n_in >= 10) ? 4 : 3;
    const float* x   = (const float*)d_in[0];
    const void*  ei  = d_in[1];
    const void*  pos = d_in[2];
    const float* Wl1 = (const float*)d_in[wi + 0];
    const float* Wr1 = (const float*)d_in[wi + 1];
    const float* b1  = (const float*)d_in[wi + 2];
    const float* Wl2 = (const float*)d_in[wi + 3];
    const float* Wr2 = (const float*)d_in[wi + 4];
    const float* b2  = (const float*)d_in[wi + 5];
    float* out = (float*)d_out;

    static int smem_set = 0;
    if (!smem_set) {
        cudaFuncSetAttribute(k_gemm, cudaFuncAttributeMaxDynamicSharedMemorySize, GEMM_SMEM);
        smem_set = 1;
    }

    k_detect<<<1, 256>>>((const unsigned*)ei, pos);
    k_init<<<2048, 256>>>(out, out_size, Wl1, Wr1, Wl2, Wr2);
    k_hist<<<(N_EDGES + 255) / 256, 256>>>(ei);
    k_scan_part<<<NBLK_SCAN, 256>>>();
    k_scan_add<<<NBLK_SCAN, 256>>>();
    k_scatter<<<(N_EDGES + 255) / 256, 256>>>(ei);

    // layer 1
    k_agg<<<(N_NODES + 7) / 8, 256>>>(x, 0);
    k_gemm<<<GEMM_GRID, 256, GEMM_SMEM>>>(x, b1, nullptr, nullptr, 0);
    // layer 2
    k_agg<<<(N_NODES + 7) / 8, 256>>>(x, 1);
    k_gemm<<<GEMM_GRID, 256, GEMM_SMEM>>>(x, b2, out, pos, 1);
}

// round 13
// speedup vs baseline: 1.1143x; 1.1143x over previous
#include <cuda_runtime.h>
#include <cuda_bf16.h>
#include <mma.h>
#include <cstdint>

using namespace nvcuda;

#define N_NODES 50000
#define N_EDGES 600000
#define FEAT 128
#define PADM 50048        // 782 * 64
#define NBLK_SCAN 196     // ceil(50000/256)

// ---------------- device scratch ----------------
__device__ int   g_idx64;
__device__ int   g_pos_arange;
__device__ int   g_cnt[N_NODES];
__device__ int   g_cursor[N_NODES];
__device__ int   g_part[N_NODES];
__device__ int   g_blksum[NBLK_SCAN];
__device__ int   g_rowstart[N_NODES + 1];
__device__ float g_inv[N_NODES];
__device__ int   g_csr[N_EDGES];

__device__ float g_agg[(size_t)PADM * FEAT];   // fp32 aggregated features (pads stay 0)
__device__ float g_h1 [(size_t)PADM * FEAT];   // fp32 layer-1 output (pads stay 0)
// B[layer][n][k], k in [0,256): k<128 -> Wl[k][n], else Wr[k-128][n]
__device__ __nv_bfloat16 g_Bhi[2 * 128 * 256];
__device__ __nv_bfloat16 g_Blo[2 * 128 * 256];

__device__ __forceinline__ int load_idx(const void* p, long long i, int is64) {
    return is64 ? (int)((const long long*)p)[i] : ((const int*)p)[i];
}
__device__ __forceinline__ unsigned pack_bf16x2(float a, float b) {
    unsigned short ua = __bfloat16_as_ushort(__float2bfloat16_rn(a));
    unsigned short ub = __bfloat16_as_ushort(__float2bfloat16_rn(b));
    return (unsigned)ua | ((unsigned)ub << 16);
}
__device__ __forceinline__ float bf16v(float v) {
    return __bfloat162float(__float2bfloat16_rn(v));
}
__device__ __forceinline__ uint32_t smem_u32(const void* p) {
    uint32_t a;
    asm("{ .reg .u64 t; cvta.to.shared.u64 t, %1; cvt.u32.u64 %0, t; }" : "=r"(a) : "l"(p));
    return a;
}
#define CP_ASYNC16(dst_u32, src_ptr) \
    asm volatile("cp.async.cg.shared.global [%0], [%1], 16;" :: "r"(dst_u32), "l"(src_ptr))
#define CP_COMMIT() asm volatile("cp.async.commit_group;" ::: "memory")
#define CP_WAIT0()  asm volatile("cp.async.wait_group 0;" ::: "memory")

// ---------------- detect index dtype + pos==arange (parallel, 1 load/thread) ----------------
__global__ void k_detect(const unsigned* __restrict__ w, const void* __restrict__ pos) {
    int tid = threadIdx.x;   // 256 threads
    int ok64 = (w[2 * tid + 1] == 0u) ? 1 : 0;
    int is64 = __syncthreads_and(ok64);
    if (tid == 0) g_idx64 = is64;
    int idx = tid * 195;     // spans [0, 49725]
    int ar = (load_idx(pos, idx, is64) == idx) ? 1 : 0;
    int arall = __syncthreads_and(ar);
    if (tid == 0) g_pos_arange = arall;
}

// ---------------- init: zero out-tail + prep weights + reset counters ----------------
__global__ void k_init(float* __restrict__ out, int out_n,
                       const float* __restrict__ Wl1, const float* __restrict__ Wr1,
                       const float* __restrict__ Wl2, const float* __restrict__ Wr2) {
    int stride = gridDim.x * blockDim.x;
    int gid = blockIdx.x * blockDim.x + threadIdx.x;

    float4 z = make_float4(0.f, 0.f, 0.f, 0.f);
    int zstart4 = g_pos_arange ? (N_NODES * FEAT) >> 2 : 0;
    int on4 = out_n >> 2;
    for (int i = zstart4 + gid; i < on4; i += stride) ((float4*)out)[i] = z;

    for (int id = gid; id < 2 * 128 * 256; id += stride) {
        int layer = id >> 15;
        int rem = id & 32767;
        int n = rem >> 8;
        int k = rem & 255;
        const float* Wl = layer ? Wl2 : Wl1;
        const float* Wr = layer ? Wr2 : Wr1;
        float v = (k < 128) ? Wl[k * 128 + n] : Wr[(k - 128) * 128 + n];
        __nv_bfloat16 h = __float2bfloat16_rn(v);
        g_Bhi[id] = h;
        g_Blo[id] = __float2bfloat16_rn(v - __bfloat162float(h));
    }

    for (int i = gid; i < N_NODES; i += stride) { g_cnt[i] = 0; g_cursor[i] = 0; }
}

__global__ void k_hist(const void* __restrict__ ei) {
    int e = blockIdx.x * blockDim.x + threadIdx.x;
    if (e >= N_EDGES) return;
    int d = load_idx(ei, (long long)N_EDGES + e, g_idx64);
    if ((unsigned)d < (unsigned)N_NODES) atomicAdd(&g_cnt[d], 1);
}

// ---------------- 2-kernel coalesced scan ----------------
__device__ __forceinline__ int blockscan256_excl(int v, int* ws) {
    int tid = threadIdx.x, lane = tid & 31, w = tid >> 5;
    int incl = v;
    #pragma unroll
    for (int o = 1; o < 32; o <<= 1) {
        int t = __shfl_up_sync(0xFFFFFFFFu, incl, o);
        if (lane >= o) incl += t;
    }
    if (lane == 31) ws[w] = incl;
    __syncthreads();
    if (w == 0) {
        int s = (lane < 8) ? ws[lane] : 0;
        #pragma unroll
        for (int o = 1; o < 8; o <<= 1) {
            int t = __shfl_up_sync(0xFFFFFFFFu, s, o);
            if (lane >= o) s += t;
        }
        if (lane < 8) ws[lane] = s;
    }
    __syncthreads();
    return incl - v + (w ? ws[w - 1] : 0);
}

__global__ void k_scan_part() {
    __shared__ int ws[8];
    int i = blockIdx.x * 256 + threadIdx.x;
    int v = (i < N_NODES) ? g_cnt[i] : 0;
    int excl = blockscan256_excl(v, ws);
    if (i < N_NODES) g_part[i] = excl;
    if (threadIdx.x == 255) g_blksum[blockIdx.x] = excl + v;
}

__global__ void k_scan_add() {
    __shared__ int ws[8];
    __shared__ int s_off;
    int tid = threadIdx.x, lane = tid & 31, w = tid >> 5;
    int bid = blockIdx.x;
    int v = (tid < NBLK_SCAN && tid < bid) ? g_blksum[tid] : 0;
    #pragma unroll
    for (int o = 16; o > 0; o >>= 1) v += __shfl_down_sync(0xFFFFFFFFu, v, o);
    if (lane == 0) ws[w] = v;
    __syncthreads();
    if (tid == 0) {
        int t = 0;
        #pragma unroll
        for (int j = 0; j < 8; j++) t += ws[j];
        s_off = t;
    }
    __syncthreads();
    int off = s_off;
    int i = bid * 256 + tid;
    if (i < N_NODES) {
        g_rowstart[i] = g_part[i] + off;
        g_inv[i] = 1.0f / fmaxf((float)g_cnt[i], 1.0f);
    }
    if (bid == NBLK_SCAN - 1 && tid == 0)
        g_rowstart[N_NODES] = off + g_blksum[bid];
}

__global__ void k_scatter(const void* __restrict__ ei) {
    int e = blockIdx.x * blockDim.x + threadIdx.x;
    if (e >= N_EDGES) return;
    int is64 = g_idx64;
    int s = load_idx(ei, e, is64);
    int d = load_idx(ei, (long long)N_EDGES + e, is64);
    if ((unsigned)d >= (unsigned)N_NODES || (unsigned)s >= (unsigned)N_NODES) return;
    int p = g_rowstart[d] + atomicAdd(&g_cursor[d], 1);
    if (p < N_EDGES) g_csr[p] = s;
}

// ---------------- aggregation: one warp per node, 4-way unrolled gather (fp32 out) ----------------
__global__ void k_agg(const float* __restrict__ feat_x, int layer2) {
    const float* __restrict__ feat = layer2 ? g_h1 : feat_x;
    int gw = (blockIdx.x * blockDim.x + threadIdx.x) >> 5;
    int lane = threadIdx.x & 31;
    if (gw >= N_NODES) return;
    int s = g_rowstart[gw], e = g_rowstart[gw + 1];
    float4 acc = make_float4(0.f, 0.f, 0.f, 0.f);
    int i = s;
    for (; i + 4 <= e; i += 4) {
        int s0 = g_csr[i + 0], s1 = g_csr[i + 1], s2 = g_csr[i + 2], s3 = g_csr[i + 3];
        float4 v0 = *(const float4*)(feat + (size_t)s0 * FEAT + lane * 4);
        float4 v1 = *(const float4*)(feat + (size_t)s1 * FEAT + lane * 4);
        float4 v2 = *(const float4*)(feat + (size_t)s2 * FEAT + lane * 4);
        float4 v3 = *(const float4*)(feat + (size_t)s3 * FEAT + lane * 4);
        acc.x += v0.x + v1.x + v2.x + v3.x;
        acc.y += v0.y + v1.y + v2.y + v3.y;
        acc.z += v0.z + v1.z + v2.z + v3.z;
        acc.w += v0.w + v1.w + v2.w + v3.w;
    }
    for (; i < e; i++) {
        int src = g_csr[i];
        float4 v = *(const float4*)(feat + (size_t)src * FEAT + lane * 4);
        acc.x += v.x; acc.y += v.y; acc.z += v.z; acc.w += v.w;
    }
    float inv = g_inv[gw];
    acc.x *= inv; acc.y *= inv; acc.z *= inv; acc.w *= inv;
    *(float4*)(g_agg + (size_t)gw * FEAT + lane * 4) = acc;
}

// ---------------- cp.async double-buffered bf16 3-split wmma GEMM (64x128 tile) ----------------
typedef wmma::fragment<wmma::matrix_a, 16, 16, 16, __nv_bfloat16, wmma::row_major> FragA;
typedef wmma::fragment<wmma::matrix_b, 16, 16, 16, __nv_bfloat16, wmma::col_major> FragB;
typedef wmma::fragment<wmma::accumulator, 16, 16, 16, float> FragC;

#define KP 40          // padded k-stride in smem (elements)
#define BUF_BYTES 30720
// per-buffer offsets (bytes): A hi 0 (5120), A lo 5120, B hi 10240 (10240), B lo 20480
#define GEMM_SMEM (2 * BUF_BYTES)   // 61440; epilogue (64x128 f32 = 32768) reuses buf0

__global__ void __launch_bounds__(256) k_gemm(
    const float* __restrict__ xin,
    const float* __restrict__ bias,
    float* __restrict__ out2, const void* __restrict__ pos, int layer2)
{
    extern __shared__ __align__(16) char smraw[];
    const float* selfF = layer2 ? g_h1 : xin;
    const __nv_bfloat16* BH = g_Bhi + (size_t)layer2 * 128 * 256;
    const __nv_bfloat16* BL = g_Blo + (size_t)layer2 * 128 * 256;

    int tid = threadIdx.x;
    int warp = tid >> 5;
    int wm = warp & 1;    // 2 M warps (32 rows each)
    int wn = warp >> 1;   // 4 N warps (32 cols each)
    int m0 = blockIdx.x * 64;

    int r = tid >> 2;          // 0..63 (A tile row)
    int cc = tid & 3;          // 0..3
    bool arow_ok = (m0 + r) < N_NODES;
    uint32_t sbase = smem_u32(smraw);

    // ---- helpers (inlined by compiler) ----
    // A global source for chunk ch
    #define A_PTR(ch) (((ch) < 4 ? g_agg : selfF) + (size_t)(m0 + r) * FEAT + ((ch) & 3) * 32 + cc * 8)
    // issue B cp.async for chunk ch into buffer b
    #define ISSUE_B(ch, b) do {                                                    \
        int _bk = (ch) * 32;                                                       \
        _Pragma("unroll")                                                          \
        for (int _j = 0; _j < 2; _j++) {                                           \
            int _seg = tid + _j * 256;                                             \
            int _rb = _seg >> 2, _cb = _seg & 3;                                   \
            size_t _bsrc = (size_t)_rb * 256 + _bk + _cb * 8;                      \
            uint32_t _dst = sbase + (b) * BUF_BYTES + 10240 + (_rb * KP + _cb * 8) * 2; \
            CP_ASYNC16(_dst, BH + _bsrc);                                          \
            CP_ASYNC16(_dst + 10240, BL + _bsrc);                                  \
        }                                                                          \
        CP_COMMIT();                                                               \
    } while (0)
    // convert A regs (f0,f1) and store to buffer b
    #define STORE_A(b, f0, f1) do {                                                \
        uint4 _hv, _lv;                                                            \
        _hv.x = pack_bf16x2((f0).x, (f0).y);                                       \
        _hv.y = pack_bf16x2((f0).z, (f0).w);                                       \
        _hv.z = pack_bf16x2((f1).x, (f1).y);                                       \
        _hv.w = pack_bf16x2((f1).z, (f1).w);                                       \
        _lv.x = pack_bf16x2((f0).x - bf16v((f0).x), (f0).y - bf16v((f0).y));       \
        _lv.y = pack_bf16x2((f0).z - bf16v((f0).z), (f0).w - bf16v((f0).w));       \
        _lv.z = pack_bf16x2((f1).x - bf16v((f1).x), (f1).y - bf16v((f1).y));       \
        _lv.w = pack_bf16x2((f1).z - bf16v((f1).z), (f1).w - bf16v((f1).w));       \
        __nv_bfloat16* _sA0 = (__nv_bfloat16*)(smraw + (b) * BUF_BYTES);           \
        __nv_bfloat16* _sA1 = (__nv_bfloat16*)(smraw + (b) * BUF_BYTES + 5120);    \
        int _dstA = r * KP + cc * 8;                                               \
        *(uint4*)(_sA0 + _dstA) = _hv;                                             \
        *(uint4*)(_sA1 + _dstA) = _lv;                                             \
    } while (0)

    // ---- prologue: stage chunk 0 into buffer 0 ----
    ISSUE_B(0, 0);
    float4 f0 = make_float4(0.f, 0.f, 0.f, 0.f), f1 = f0;
    if (arow_ok) {
        const float* p = A_PTR(0);
        f0 = *(const float4*)p;
        f1 = *(const float4*)(p + 4);
    }
    STORE_A(0, f0, f1);
    CP_WAIT0();
    __syncthreads();

    FragC c[2][2];
    #pragma unroll
    for (int i = 0; i < 2; i++)
        #pragma unroll
        for (int j = 0; j < 2; j++)
            wmma::fill_fragment(c[i][j], 0.0f);

    #pragma unroll 1
    for (int ch = 0; ch < 8; ch++) {
        int cur = ch & 1, nxt = cur ^ 1;

        // prefetch next chunk: B via cp.async (direct to smem), A into registers
        float4 n0 = make_float4(0.f, 0.f, 0.f, 0.f), n1 = n0;
        if (ch < 7) {
            ISSUE_B(ch + 1, nxt);
            if (arow_ok) {
                const float* p = A_PTR(ch + 1);
                n0 = *(const float4*)p;
                n1 = *(const float4*)(p + 4);
            }
        }

        // compute from current buffer while prefetch is in flight
        __nv_bfloat16* sA0 = (__nv_bfloat16*)(smraw + cur * BUF_BYTES);
        __nv_bfloat16* sA1 = (__nv_bfloat16*)(smraw + cur * BUF_BYTES + 5120);
        __nv_bfloat16* sB0 = (__nv_bfloat16*)(smraw + cur * BUF_BYTES + 10240);
        __nv_bfloat16* sB1 = (__nv_bfloat16*)(smraw + cur * BUF_BYTES + 20480);
        #pragma unroll
        for (int ks = 0; ks < 2; ks++) {
            FragA ah[2], al[2];
            #pragma unroll
            for (int i = 0; i < 2; i++) {
                wmma::load_matrix_sync(ah[i], sA0 + (wm * 32 + i * 16) * KP + ks * 16, KP);
                wmma::load_matrix_sync(al[i], sA1 + (wm * 32 + i * 16) * KP + ks * 16, KP);
            }
            FragB bh[2], bl[2];
            #pragma unroll
            for (int j = 0; j < 2; j++) {
                wmma::load_matrix_sync(bh[j], sB0 + (wn * 32 + j * 16) * KP + ks * 16, KP);
                wmma::load_matrix_sync(bl[j], sB1 + (wn * 32 + j * 16) * KP + ks * 16, KP);
            }
            #pragma unroll
            for (int i = 0; i < 2; i++)
                #pragma unroll
                for (int j = 0; j < 2; j++) {
                    wmma::mma_sync(c[i][j], ah[i], bh[j], c[i][j]);
                    wmma::mma_sync(c[i][j], al[i], bh[j], c[i][j]);
                    wmma::mma_sync(c[i][j], ah[i], bl[j], c[i][j]);
                }
        }

        if (ch < 7) {
            STORE_A(nxt, n0, n1);
            CP_WAIT0();
        }
        __syncthreads();
    }

    // epilogue: single-pass 64 x 128 f32 through smem (reuses buffers)
    float* cs = (float*)smraw;
    int is64 = g_idx64;
    #pragma unroll
    for (int i = 0; i < 2; i++)
        #pragma unroll
        for (int j = 0; j < 2; j++)
            wmma::store_matrix_sync(&cs[(wm * 32 + i * 16) * 128 + wn * 32 + j * 16],
                                    c[i][j], 128, wmma::mem_row_major);
    __syncthreads();

    #pragma unroll
    for (int it = 0; it < 8; it++) {
        int idx = (it * 256 + tid) * 4;    // 0..8188 -> 64x128
        int m = idx >> 7;
        int n = idx & 127;
        int row = m0 + m;
        if (row < N_NODES) {
            float v0 = fmaxf(cs[idx + 0] + bias[n + 0], 0.0f);
            float v1 = fmaxf(cs[idx + 1] + bias[n + 1], 0.0f);
            float v2 = fmaxf(cs[idx + 2] + bias[n + 2], 0.0f);
            float v3 = fmaxf(cs[idx + 3] + bias[n + 3], 0.0f);
            if (!layer2) {
                *(float4*)(g_h1 + (size_t)row * FEAT + n) = make_float4(v0, v1, v2, v3);
            } else {
                long long orow = (long long)load_idx(pos, row, is64);
                *(float4*)(out2 + (size_t)orow * FEAT + n) = make_float4(v0, v1, v2, v3);
            }
        }
    }
}

// ---------------- launch ----------------
extern "C" void kernel_launch(void* const* d_in, const int* in_sizes, int n_in,
                              void* d_out, int out_size) {
    int wi = (n_in >= 10) ? 4 : 3;
    const float* x   = (const float*)d_in[0];
    const void*  ei  = d_in[1];
    const void*  pos = d_in[2];
    const float* Wl1 = (const float*)d_in[wi + 0];
    const float* Wr1 = (const float*)d_in[wi + 1];
    const float* b1  = (const float*)d_in[wi + 2];
    const float* Wl2 = (const float*)d_in[wi + 3];
    const float* Wr2 = (const float*)d_in[wi + 4];
    const float* b2  = (const float*)d_in[wi + 5];
    float* out = (float*)d_out;

    static int smem_set = 0;
    if (!smem_set) {
        cudaFuncSetAttribute(k_gemm, cudaFuncAttributeMaxDynamicSharedMemorySize, GEMM_SMEM);
        smem_set = 1;
    }

    k_detect<<<1, 256>>>((const unsigned*)ei, pos);
    k_init<<<2048, 256>>>(out, out_size, Wl1, Wr1, Wl2, Wr2);
    k_hist<<<(N_EDGES + 255) / 256, 256>>>(ei);
    k_scan_part<<<NBLK_SCAN, 256>>>();
    k_scan_add<<<NBLK_SCAN, 256>>>();
    k_scatter<<<(N_EDGES + 255) / 256, 256>>>(ei);

    // layer 1
    k_agg<<<(N_NODES + 7) / 8, 256>>>(x, 0);
    k_gemm<<<PADM / 64, 256, GEMM_SMEM>>>(x, b1, nullptr, nullptr, 0);
    // layer 2
    k_agg<<<(N_NODES + 7) / 8, 256>>>(x, 1);
    k_gemm<<<PADM / 64, 256, GEMM_SMEM>>>(x, b2, out, pos, 1);
}

// round 14
// speedup vs baseline: 1.1153x; 1.0009x over previous
#include <cuda_runtime.h>
#include <cuda_bf16.h>
#include <mma.h>
#include <cstdint>

using namespace nvcuda;

#define N_NODES 50000
#define N_EDGES 600000
#define FEAT 128
#define PADM 50048        // 782 * 64
#define NBLK_SCAN 196     // ceil(50000/256)

// ---------------- device scratch ----------------
__device__ int   g_idx64;
__device__ int   g_pos_arange;
__device__ int   g_cnt[N_NODES];
__device__ int   g_cursor[N_NODES];
__device__ int   g_part[N_NODES];
__device__ int   g_blksum[NBLK_SCAN];
__device__ int   g_rowstart[N_NODES + 1];
__device__ float g_inv[N_NODES];
__device__ int   g_csr[N_EDGES];

__device__ float g_agg[(size_t)PADM * FEAT];   // fp32 aggregated features (pads stay 0)
__device__ float g_h1 [(size_t)PADM * FEAT];   // fp32 layer-1 output (pads stay 0)
// B[layer][n][k], k in [0,256): k<128 -> Wl[k][n], else Wr[k-128][n]
__device__ __nv_bfloat16 g_Bhi[2 * 128 * 256];
__device__ __nv_bfloat16 g_Blo[2 * 128 * 256];

__device__ __forceinline__ int load_idx(const void* p, long long i, int is64) {
    return is64 ? (int)((const long long*)p)[i] : ((const int*)p)[i];
}
__device__ __forceinline__ unsigned pack_bf16x2(float a, float b) {
    unsigned short ua = __bfloat16_as_ushort(__float2bfloat16_rn(a));
    unsigned short ub = __bfloat16_as_ushort(__float2bfloat16_rn(b));
    return (unsigned)ua | ((unsigned)ub << 16);
}
__device__ __forceinline__ float bf16v(float v) {
    return __bfloat162float(__float2bfloat16_rn(v));
}
__device__ __forceinline__ uint32_t smem_u32(const void* p) {
    uint32_t a;
    asm("{ .reg .u64 t; cvta.to.shared.u64 t, %1; cvt.u32.u64 %0, t; }" : "=r"(a) : "l"(p));
    return a;
}
#define CP_ASYNC16(dst_u32, src_ptr) \
    asm volatile("cp.async.cg.shared.global [%0], [%1], 16;" :: "r"(dst_u32), "l"(src_ptr))
#define CP_COMMIT() asm volatile("cp.async.commit_group;" ::: "memory")
#define CP_WAIT0()  asm volatile("cp.async.wait_group 0;" ::: "memory")

// ---------------- detect index dtype + pos==arange (parallel, 1 load/thread) ----------------
__global__ void k_detect(const unsigned* __restrict__ w, const void* __restrict__ pos) {
    int tid = threadIdx.x;   // 256 threads
    int ok64 = (w[2 * tid + 1] == 0u) ? 1 : 0;
    int is64 = __syncthreads_and(ok64);
    if (tid == 0) g_idx64 = is64;
    int idx = tid * 195;     // spans [0, 49725]
    int ar = (load_idx(pos, idx, is64) == idx) ? 1 : 0;
    int arall = __syncthreads_and(ar);
    if (tid == 0) g_pos_arange = arall;
}

// ---------------- reset counters (critical path; tiny) ----------------
__global__ void k_reset() {
    int i = blockIdx.x * blockDim.x + threadIdx.x;
    if (i < N_NODES) { g_cnt[i] = 0; g_cursor[i] = 0; }
}

// ---------------- init (side stream): zero out-tail + prep weights ----------------
__global__ void k_init(float* __restrict__ out, int out_n,
                       const float* __restrict__ Wl1, const float* __restrict__ Wr1,
                       const float* __restrict__ Wl2, const float* __restrict__ Wr2) {
    int stride = gridDim.x * blockDim.x;
    int gid = blockIdx.x * blockDim.x + threadIdx.x;

    float4 z = make_float4(0.f, 0.f, 0.f, 0.f);
    int zstart4 = g_pos_arange ? (N_NODES * FEAT) >> 2 : 0;
    int on4 = out_n >> 2;
    for (int i = zstart4 + gid; i < on4; i += stride) ((float4*)out)[i] = z;

    for (int id = gid; id < 2 * 128 * 256; id += stride) {
        int layer = id >> 15;
        int rem = id & 32767;
        int n = rem >> 8;
        int k = rem & 255;
        const float* Wl = layer ? Wl2 : Wl1;
        const float* Wr = layer ? Wr2 : Wr1;
        float v = (k < 128) ? Wl[k * 128 + n] : Wr[(k - 128) * 128 + n];
        __nv_bfloat16 h = __float2bfloat16_rn(v);
        g_Bhi[id] = h;
        g_Blo[id] = __float2bfloat16_rn(v - __bfloat162float(h));
    }
}

__global__ void k_hist(const void* __restrict__ ei) {
    int e = blockIdx.x * blockDim.x + threadIdx.x;
    if (e >= N_EDGES) return;
    int d = load_idx(ei, (long long)N_EDGES + e, g_idx64);
    if ((unsigned)d < (unsigned)N_NODES) atomicAdd(&g_cnt[d], 1);
}

// ---------------- 2-kernel coalesced scan ----------------
__device__ __forceinline__ int blockscan256_excl(int v, int* ws) {
    int tid = threadIdx.x, lane = tid & 31, w = tid >> 5;
    int incl = v;
    #pragma unroll
    for (int o = 1; o < 32; o <<= 1) {
        int t = __shfl_up_sync(0xFFFFFFFFu, incl, o);
        if (lane >= o) incl += t;
    }
    if (lane == 31) ws[w] = incl;
    __syncthreads();
    if (w == 0) {
        int s = (lane < 8) ? ws[lane] : 0;
        #pragma unroll
        for (int o = 1; o < 8; o <<= 1) {
            int t = __shfl_up_sync(0xFFFFFFFFu, s, o);
            if (lane >= o) s += t;
        }
        if (lane < 8) ws[lane] = s;
    }
    __syncthreads();
    return incl - v + (w ? ws[w - 1] : 0);
}

__global__ void k_scan_part() {
    __shared__ int ws[8];
    int i = blockIdx.x * 256 + threadIdx.x;
    int v = (i < N_NODES) ? g_cnt[i] : 0;
    int excl = blockscan256_excl(v, ws);
    if (i < N_NODES) g_part[i] = excl;
    if (threadIdx.x == 255) g_blksum[blockIdx.x] = excl + v;
}

__global__ void k_scan_add() {
    __shared__ int ws[8];
    __shared__ int s_off;
    int tid = threadIdx.x, lane = tid & 31, w = tid >> 5;
    int bid = blockIdx.x;
    int v = (tid < NBLK_SCAN && tid < bid) ? g_blksum[tid] : 0;
    #pragma unroll
    for (int o = 16; o > 0; o >>= 1) v += __shfl_down_sync(0xFFFFFFFFu, v, o);
    if (lane == 0) ws[w] = v;
    __syncthreads();
    if (tid == 0) {
        int t = 0;
        #pragma unroll
        for (int j = 0; j < 8; j++) t += ws[j];
        s_off = t;
    }
    __syncthreads();
    int off = s_off;
    int i = bid * 256 + tid;
    if (i < N_NODES) {
        g_rowstart[i] = g_part[i] + off;
        g_inv[i] = 1.0f / fmaxf((float)g_cnt[i], 1.0f);
    }
    if (bid == NBLK_SCAN - 1 && tid == 0)
        g_rowstart[N_NODES] = off + g_blksum[bid];
}

__global__ void k_scatter(const void* __restrict__ ei) {
    int e = blockIdx.x * blockDim.x + threadIdx.x;
    if (e >= N_EDGES) return;
    int is64 = g_idx64;
    int s = load_idx(ei, e, is64);
    int d = load_idx(ei, (long long)N_EDGES + e, is64);
    if ((unsigned)d >= (unsigned)N_NODES || (unsigned)s >= (unsigned)N_NODES) return;
    int p = g_rowstart[d] + atomicAdd(&g_cursor[d], 1);
    if (p < N_EDGES) g_csr[p] = s;
}

// ---------------- aggregation: one warp per node, 4-way unrolled gather (fp32 out) ----------------
__global__ void k_agg(const float* __restrict__ feat_x, int layer2) {
    const float* __restrict__ feat = layer2 ? g_h1 : feat_x;
    int gw = (blockIdx.x * blockDim.x + threadIdx.x) >> 5;
    int lane = threadIdx.x & 31;
    if (gw >= N_NODES) return;
    int s = g_rowstart[gw], e = g_rowstart[gw + 1];
    float4 acc = make_float4(0.f, 0.f, 0.f, 0.f);
    int i = s;
    for (; i + 4 <= e; i += 4) {
        int s0 = g_csr[i + 0], s1 = g_csr[i + 1], s2 = g_csr[i + 2], s3 = g_csr[i + 3];
        float4 v0 = *(const float4*)(feat + (size_t)s0 * FEAT + lane * 4);
        float4 v1 = *(const float4*)(feat + (size_t)s1 * FEAT + lane * 4);
        float4 v2 = *(const float4*)(feat + (size_t)s2 * FEAT + lane * 4);
        float4 v3 = *(const float4*)(feat + (size_t)s3 * FEAT + lane * 4);
        acc.x += v0.x + v1.x + v2.x + v3.x;
        acc.y += v0.y + v1.y + v2.y + v3.y;
        acc.z += v0.z + v1.z + v2.z + v3.z;
        acc.w += v0.w + v1.w + v2.w + v3.w;
    }
    for (; i < e; i++) {
        int src = g_csr[i];
        float4 v = *(const float4*)(feat + (size_t)src * FEAT + lane * 4);
        acc.x += v.x; acc.y += v.y; acc.z += v.z; acc.w += v.w;
    }
    float inv = g_inv[gw];
    acc.x *= inv; acc.y *= inv; acc.z *= inv; acc.w *= inv;
    *(float4*)(g_agg + (size_t)gw * FEAT + lane * 4) = acc;
}

// ---------------- cp.async double-buffered bf16 3-split wmma GEMM (64x128 tile) ----------------
typedef wmma::fragment<wmma::matrix_a, 16, 16, 16, __nv_bfloat16, wmma::row_major> FragA;
typedef wmma::fragment<wmma::matrix_b, 16, 16, 16, __nv_bfloat16, wmma::col_major> FragB;
typedef wmma::fragment<wmma::accumulator, 16, 16, 16, float> FragC;

#define KP 40          // padded k-stride in smem (elements)
#define BUF_BYTES 30720
#define GEMM_SMEM (2 * BUF_BYTES)   // 61440; epilogue (64x128 f32 = 32768) reuses buf0

__global__ void __launch_bounds__(256) k_gemm(
    const float* __restrict__ xin,
    const float* __restrict__ bias,
    float* __restrict__ out2, const void* __restrict__ pos, int layer2)
{
    extern __shared__ __align__(16) char smraw[];
    const float* selfF = layer2 ? g_h1 : xin;
    const __nv_bfloat16* BH = g_Bhi + (size_t)layer2 * 128 * 256;
    const __nv_bfloat16* BL = g_Blo + (size_t)layer2 * 128 * 256;

    int tid = threadIdx.x;
    int warp = tid >> 5;
    int wm = warp & 1;    // 2 M warps (32 rows each)
    int wn = warp >> 1;   // 4 N warps (32 cols each)
    int m0 = blockIdx.x * 64;

    int r = tid >> 2;          // 0..63 (A tile row)
    int cc = tid & 3;          // 0..3
    bool arow_ok = (m0 + r) < N_NODES;
    uint32_t sbase = smem_u32(smraw);

    #define A_PTR(ch) (((ch) < 4 ? g_agg : selfF) + (size_t)(m0 + r) * FEAT + ((ch) & 3) * 32 + cc * 8)
    #define ISSUE_B(ch, b) do {                                                    \
        int _bk = (ch) * 32;                                                       \
        _Pragma("unroll")                                                          \
        for (int _j = 0; _j < 2; _j++) {                                           \
            int _seg = tid + _j * 256;                                             \
            int _rb = _seg >> 2, _cb = _seg & 3;                                   \
            size_t _bsrc = (size_t)_rb * 256 + _bk + _cb * 8;                      \
            uint32_t _dst = sbase + (b) * BUF_BYTES + 10240 + (_rb * KP + _cb * 8) * 2; \
            CP_ASYNC16(_dst, BH + _bsrc);                                          \
            CP_ASYNC16(_dst + 10240, BL + _bsrc);                                  \
        }                                                                          \
        CP_COMMIT();                                                               \
    } while (0)
    #define STORE_A(b, f0, f1) do {                                                \
        uint4 _hv, _lv;                                                            \
        _hv.x = pack_bf16x2((f0).x, (f0).y);                                       \
        _hv.y = pack_bf16x2((f0).z, (f0).w);                                       \
        _hv.z = pack_bf16x2((f1).x, (f1).y);                                       \
        _hv.w = pack_bf16x2((f1).z, (f1).w);                                       \
        _lv.x = pack_bf16x2((f0).x - bf16v((f0).x), (f0).y - bf16v((f0).y));       \
        _lv.y = pack_bf16x2((f0).z - bf16v((f0).z), (f0).w - bf16v((f0).w));       \
        _lv.z = pack_bf16x2((f1).x - bf16v((f1).x), (f1).y - bf16v((f1).y));       \
        _lv.w = pack_bf16x2((f1).z - bf16v((f1).z), (f1).w - bf16v((f1).w));       \
        __nv_bfloat16* _sA0 = (__nv_bfloat16*)(smraw + (b) * BUF_BYTES);           \
        __nv_bfloat16* _sA1 = (__nv_bfloat16*)(smraw + (b) * BUF_BYTES + 5120);    \
        int _dstA = r * KP + cc * 8;                                               \
        *(uint4*)(_sA0 + _dstA) = _hv;                                             \
        *(uint4*)(_sA1 + _dstA) = _lv;                                             \
    } while (0)

    // prologue: stage chunk 0 into buffer 0
    ISSUE_B(0, 0);
    float4 f0 = make_float4(0.f, 0.f, 0.f, 0.f), f1 = f0;
    if (arow_ok) {
        const float* p = A_PTR(0);
        f0 = *(const float4*)p;
        f1 = *(const float4*)(p + 4);
    }
    STORE_A(0, f0, f1);
    CP_WAIT0();
    __syncthreads();

    FragC c[2][2];
    #pragma unroll
    for (int i = 0; i < 2; i++)
        #pragma unroll
        for (int j = 0; j < 2; j++)
            wmma::fill_fragment(c[i][j], 0.0f);

    #pragma unroll 1
    for (int ch = 0; ch < 8; ch++) {
        int cur = ch & 1, nxt = cur ^ 1;

        float4 n0 = make_float4(0.f, 0.f, 0.f, 0.f), n1 = n0;
        if (ch < 7) {
            ISSUE_B(ch + 1, nxt);
            if (arow_ok) {
                const float* p = A_PTR(ch + 1);
                n0 = *(const float4*)p;
                n1 = *(const float4*)(p + 4);
            }
        }

        __nv_bfloat16* sA0 = (__nv_bfloat16*)(smraw + cur * BUF_BYTES);
        __nv_bfloat16* sA1 = (__nv_bfloat16*)(smraw + cur * BUF_BYTES + 5120);
        __nv_bfloat16* sB0 = (__nv_bfloat16*)(smraw + cur * BUF_BYTES + 10240);
        __nv_bfloat16* sB1 = (__nv_bfloat16*)(smraw + cur * BUF_BYTES + 20480);
        #pragma unroll
        for (int ks = 0; ks < 2; ks++) {
            FragA ah[2], al[2];
            #pragma unroll
            for (int i = 0; i < 2; i++) {
                wmma::load_matrix_sync(ah[i], sA0 + (wm * 32 + i * 16) * KP + ks * 16, KP);
                wmma::load_matrix_sync(al[i], sA1 + (wm * 32 + i * 16) * KP + ks * 16, KP);
            }
            FragB bh[2], bl[2];
            #pragma unroll
            for (int j = 0; j < 2; j++) {
                wmma::load_matrix_sync(bh[j], sB0 + (wn * 32 + j * 16) * KP + ks * 16, KP);
                wmma::load_matrix_sync(bl[j], sB1 + (wn * 32 + j * 16) * KP + ks * 16, KP);
            }
            #pragma unroll
            for (int i = 0; i < 2; i++)
                #pragma unroll
                for (int j = 0; j < 2; j++) {
                    wmma::mma_sync(c[i][j], ah[i], bh[j], c[i][j]);
                    wmma::mma_sync(c[i][j], al[i], bh[j], c[i][j]);
                    wmma::mma_sync(c[i][j], ah[i], bl[j], c[i][j]);
                }
        }

        if (ch < 7) {
            STORE_A(nxt, n0, n1);
            CP_WAIT0();
        }
        __syncthreads();
    }

    // epilogue: single-pass 64 x 128 f32 through smem (reuses buffers)
    float* cs = (float*)smraw;
    int is64 = g_idx64;
    #pragma unroll
    for (int i = 0; i < 2; i++)
        #pragma unroll
        for (int j = 0; j < 2; j++)
            wmma::store_matrix_sync(&cs[(wm * 32 + i * 16) * 128 + wn * 32 + j * 16],
                                    c[i][j], 128, wmma::mem_row_major);
    __syncthreads();

    #pragma unroll
    for (int it = 0; it < 8; it++) {
        int idx = (it * 256 + tid) * 4;    // 0..8188 -> 64x128
        int m = idx >> 7;
        int n = idx & 127;
        int row = m0 + m;
        if (row < N_NODES) {
            float v0 = fmaxf(cs[idx + 0] + bias[n + 0], 0.0f);
            float v1 = fmaxf(cs[idx + 1] + bias[n + 1], 0.0f);
            float v2 = fmaxf(cs[idx + 2] + bias[n + 2], 0.0f);
            float v3 = fmaxf(cs[idx + 3] + bias[n + 3], 0.0f);
            if (!layer2) {
                *(float4*)(g_h1 + (size_t)row * FEAT + n) = make_float4(v0, v1, v2, v3);
            } else {
                long long orow = (long long)load_idx(pos, row, is64);
                *(float4*)(out2 + (size_t)orow * FEAT + n) = make_float4(v0, v1, v2, v3);
            }
        }
    }
}

// ---------------- launch (fork/join: init on side stream, hidden under CSR build) ----------------
extern "C" void kernel_launch(void* const* d_in, const int* in_sizes, int n_in,
                              void* d_out, int out_size) {
    int wi = (n_in >= 10) ? 4 : 3;
    const float* x   = (const float*)d_in[0];
    const void*  ei  = d_in[1];
    const void*  pos = d_in[2];
    const float* Wl1 = (const float*)d_in[wi + 0];
    const float* Wr1 = (const float*)d_in[wi + 1];
    const float* b1  = (const float*)d_in[wi + 2];
    const float* Wl2 = (const float*)d_in[wi + 3];
    const float* Wr2 = (const float*)d_in[wi + 4];
    const float* b2  = (const float*)d_in[wi + 5];
    float* out = (float*)d_out;

    static cudaStream_t s_side = nullptr;
    static cudaEvent_t ev_fork = nullptr, ev_join = nullptr;
    static int smem_set = 0;
    if (!smem_set) {
        cudaFuncSetAttribute(k_gemm, cudaFuncAttributeMaxDynamicSharedMemorySize, GEMM_SMEM);
        cudaStreamCreateWithFlags(&s_side, cudaStreamNonBlocking);
        cudaEventCreateWithFlags(&ev_fork, cudaEventDisableTiming);
        cudaEventCreateWithFlags(&ev_join, cudaEventDisableTiming);
        smem_set = 1;
    }

    // main (legacy) stream: detect feeds everything
    k_detect<<<1, 256>>>((const unsigned*)ei, pos);

    // fork: init (weights + out-zero) runs beside the CSR build
    cudaEventRecord(ev_fork, 0);
    cudaStreamWaitEvent(s_side, ev_fork, 0);
    k_init<<<2048, 256, 0, s_side>>>(out, out_size, Wl1, Wr1, Wl2, Wr2);
    cudaEventRecord(ev_join, s_side);

    // critical path: CSR build + layer-1 aggregation
    k_reset<<<NBLK_SCAN, 256>>>();
    k_hist<<<(N_EDGES + 255) / 256, 256>>>(ei);
    k_scan_part<<<NBLK_SCAN, 256>>>();
    k_scan_add<<<NBLK_SCAN, 256>>>();
    k_scatter<<<(N_EDGES + 255) / 256, 256>>>(ei);
    k_agg<<<(N_NODES + 7) / 8, 256>>>(x, 0);

    // join: gemm1 needs weights (init)
    cudaStreamWaitEvent(0, ev_join, 0);
    k_gemm<<<PADM / 64, 256, GEMM_SMEM>>>(x, b1, nullptr, nullptr, 0);
    k_agg<<<(N_NODES + 7) / 8, 256>>>(x, 1);
    k_gemm<<<PADM / 64, 256, GEMM_SMEM>>>(x, b2, out, pos, 1);
}